// round 4
// baseline (speedup 1.0000x reference)
#include <cuda_runtime.h>
#include <cuda_bf16.h>

// ---------------------------------------------------------------------------
// SAGE 2-layer GraphSAGE, mean aggregation.
//   agg1 = mean_{src->i} x[src];  h = relu(x@Ws1 + agg1@Wn1 + b1)
//   out  = h@Ws2 + mean_{src->i} (h@Wn2)[src] + b2   (aggregation is linear)
// Index dtype (int32 vs int64) detected at runtime on-device.
// ---------------------------------------------------------------------------

#define N_NODES 100000
#define N_EDGES 1600000
#define D_IN    128
#define D_HID   128
#define D_OUT   64

// -------------------- device scratch (no allocations allowed) --------------
__device__ int   g_i64;                 // 1 if edge indices are int64
__device__ int   g_deg[N_NODES];
__device__ int   g_rowptr[N_NODES + 1];
__device__ int   g_cursor[N_NODES];
__device__ int   g_csrsrc[N_EDGES];
__device__ float g_agg[(size_t)N_NODES * D_IN];
__device__ float g_h[(size_t)N_NODES * D_HID];
__device__ float g_t[(size_t)N_NODES * D_OUT];

// -------------------- dtype detection --------------------------------------
// int64 values in [0, 2^31) have zero odd 32-bit words (little-endian).
// For int32 data the odd words are random node ids (virtually never all 0).
__global__ void k_detect(const void* srcbuf) {
    const int* w = (const int*)srcbuf;
    __shared__ int odd_nz;
    if (threadIdx.x == 0) odd_nz = 0;
    __syncthreads();
    int bad = 0;
    for (int i = threadIdx.x; i < 1024; i += blockDim.x)
        if (w[2 * i + 1] != 0) bad = 1;           // stays within 8KB of buffer
    if (bad) atomicOr(&odd_nz, 1);
    __syncthreads();
    if (threadIdx.x == 0) g_i64 = (odd_nz == 0) ? 1 : 0;
}

__device__ __forceinline__ int idx_at(const void* p, int e, int i64) {
    return i64 ? (int)((const long long*)p)[e] : ((const int*)p)[e];
}

// -------------------- CSR build ---------------------------------------------
__global__ void k_zero_deg() {
    int i = blockIdx.x * blockDim.x + threadIdx.x;
    if (i < N_NODES) g_deg[i] = 0;
}

__global__ void k_hist(const void* dst) {
    int e = blockIdx.x * blockDim.x + threadIdx.x;
    int i64 = g_i64;
    if (e < N_EDGES) {
        int d = idx_at(dst, e, i64);
        if (d >= 0 && d < N_NODES) atomicAdd(&g_deg[d], 1);
    }
}

// single-block exclusive scan of g_deg -> g_rowptr (+ cursor copy)
__global__ void k_scan() {
    __shared__ int sums[1024];
    const int t = threadIdx.x;
    const int chunk = (N_NODES + 1023) / 1024;  // 98
    int beg = t * chunk;
    int end = beg + chunk; if (end > N_NODES) end = N_NODES;
    int s = 0;
    for (int i = beg; i < end; i++) s += g_deg[i];
    sums[t] = s;
    __syncthreads();
    for (int off = 1; off < 1024; off <<= 1) {
        int v = (t >= off) ? sums[t - off] : 0;
        __syncthreads();
        sums[t] += v;
        __syncthreads();
    }
    int prefix = (t == 0) ? 0 : sums[t - 1];
    for (int i = beg; i < end; i++) {
        g_rowptr[i] = prefix;
        g_cursor[i] = prefix;
        prefix += g_deg[i];
    }
    if (t == 1023) g_rowptr[N_NODES] = sums[1023];
}

__global__ void k_scatter(const void* src, const void* dst) {
    int e = blockIdx.x * blockDim.x + threadIdx.x;
    int i64 = g_i64;
    if (e < N_EDGES) {
        int d = idx_at(dst, e, i64);
        int s = idx_at(src, e, i64);
        if (d >= 0 && d < N_NODES && s >= 0 && s < N_NODES) {
            int pos = atomicAdd(&g_cursor[d], 1);
            g_csrsrc[pos] = s;
        }
    }
}

// -------------------- aggregation kernels ----------------------------------
// layer 1: one warp per node, 128 floats = 32 float4 lanes
__global__ void k_agg128(const float* __restrict__ x) {
    int gtid = blockIdx.x * blockDim.x + threadIdx.x;
    int node = gtid >> 5;
    int lane = gtid & 31;
    if (node >= N_NODES) return;
    int beg = g_rowptr[node];
    int end = g_rowptr[node + 1];
    const float4* x4 = (const float4*)x;
    float ax = 0.f, ay = 0.f, az = 0.f, aw = 0.f;
    for (int j = beg; j < end; j++) {
        int s = g_csrsrc[j];
        float4 v = x4[(size_t)s * 32 + lane];
        ax += v.x; ay += v.y; az += v.z; aw += v.w;
    }
    int deg = end - beg;
    float inv = 1.0f / (float)(deg > 0 ? deg : 1);
    float4 r = make_float4(ax * inv, ay * inv, az * inv, aw * inv);
    ((float4*)g_agg)[(size_t)node * 32 + lane] = r;
}

// layer 2: one warp per node over g_t (64 floats = 32 float2 lanes), add to out
__global__ void k_agg64(float* __restrict__ out) {
    int gtid = blockIdx.x * blockDim.x + threadIdx.x;
    int node = gtid >> 5;
    int lane = gtid & 31;
    if (node >= N_NODES) return;
    int beg = g_rowptr[node];
    int end = g_rowptr[node + 1];
    const float2* t2 = (const float2*)g_t;
    float ax = 0.f, ay = 0.f;
    for (int j = beg; j < end; j++) {
        int s = g_csrsrc[j];
        float2 v = t2[(size_t)s * 32 + lane];
        ax += v.x; ay += v.y;
    }
    int deg = end - beg;
    float inv = 1.0f / (float)(deg > 0 ? deg : 1);
    float2* o2 = (float2*)out;
    float2 cur = o2[(size_t)node * 32 + lane];
    cur.x += ax * inv;
    cur.y += ay * inv;
    o2[(size_t)node * 32 + lane] = cur;
}

// -------------------- simple per-node GEMV layers ---------------------------
// layer 1: one block (128 threads) per node.
//   h[n][j] = relu( b1[j] + sum_k x[n][k]*Ws1[k][j] + sum_k agg[n][k]*Wn1[k][j] )
__global__ __launch_bounds__(128) void k_l1(
    const float* __restrict__ x, const float* __restrict__ Ws,
    const float* __restrict__ Wn, const float* __restrict__ b1) {
    int n = blockIdx.x;
    int j = threadIdx.x;
    __shared__ float xs[D_IN];
    __shared__ float as[D_IN];
    xs[j] = x[(size_t)n * D_IN + j];
    as[j] = g_agg[(size_t)n * D_IN + j];
    __syncthreads();
    float acc = b1[j];
#pragma unroll 8
    for (int k = 0; k < D_IN; k++) {
        acc = fmaf(xs[k], Ws[k * D_HID + j], acc);
        acc = fmaf(as[k], Wn[k * D_HID + j], acc);
    }
    g_h[(size_t)n * D_HID + j] = fmaxf(acc, 0.f);
}

// layer 2: one block (128 threads) per node.
//   j <  64 : out[n][j]   = b2[j] + sum_k h[n][k]*Ws2[k][j]
//   j >= 64 : g_t[n][j-64]=         sum_k h[n][k]*Wn2[k][j-64]
__global__ __launch_bounds__(128) void k_l2(
    const float* __restrict__ Ws2, const float* __restrict__ Wn2,
    const float* __restrict__ b2, float* __restrict__ out) {
    int n = blockIdx.x;
    int j = threadIdx.x;
    __shared__ float hs[D_HID];
    hs[j] = g_h[(size_t)n * D_HID + j];
    __syncthreads();
    if (j < D_OUT) {
        float acc = b2[j];
#pragma unroll 8
        for (int k = 0; k < D_HID; k++)
            acc = fmaf(hs[k], Ws2[k * D_OUT + j], acc);
        out[(size_t)n * D_OUT + j] = acc;
    } else {
        int jj = j - D_OUT;
        float acc = 0.f;
#pragma unroll 8
        for (int k = 0; k < D_HID; k++)
            acc = fmaf(hs[k], Wn2[k * D_OUT + jj], acc);
        g_t[(size_t)n * D_OUT + jj] = acc;
    }
}

// ---------------------------------------------------------------------------
extern "C" void kernel_launch(void* const* d_in, const int* in_sizes, int n_in,
                              void* d_out, int out_size) {
    const float* x   = (const float*)d_in[0];
    const void*  src = d_in[1];
    const void*  dst = d_in[2];
    const float* Ws1 = (const float*)d_in[3];
    const float* Wn1 = (const float*)d_in[4];
    const float* b1  = (const float*)d_in[5];
    const float* Ws2 = (const float*)d_in[6];
    const float* Wn2 = (const float*)d_in[7];
    const float* b2  = (const float*)d_in[8];
    float* out = (float*)d_out;

    // 0) index dtype detection (stream-ordered before any index consumer)
    k_detect<<<1, 256>>>(src);

    // 1) CSR build
    k_zero_deg<<<(N_NODES + 255) / 256, 256>>>();
    k_hist<<<(N_EDGES + 255) / 256, 256>>>(dst);
    k_scan<<<1, 1024>>>();
    k_scatter<<<(N_EDGES + 255) / 256, 256>>>(src, dst);

    // 2) layer 1
    k_agg128<<<(N_NODES * 32 + 255) / 256, 256>>>(x);
    k_l1<<<N_NODES, 128>>>(x, Ws1, Wn1, b1);

    // 3) layer 2 (transform first, aggregate 64-wide afterwards)
    k_l2<<<N_NODES, 128>>>(Ws2, Wn2, b2, out);
    k_agg64<<<(N_NODES * 32 + 255) / 256, 256>>>(out);
}

// round 6
// speedup vs baseline: 2.5399x; 2.5399x over previous
#include <cuda_runtime.h>
#include <cuda_bf16.h>

// ---------------------------------------------------------------------------
// SAGE 2-layer GraphSAGE, mean aggregation.
//   agg1 = mean_{src->i} x[src];  h = relu(x@Ws1 + agg1@Wn1 + b1)
//   out  = h@Ws2 + mean_{src->i} (h@Wn2)[src] + b2   (aggregation is linear)
// Index dtype (int32 vs int64) detected at runtime on-device.
// RULE LEARNED THE HARD WAY: never pass __device__ globals as kernel args
// from host code — reference them directly in device code.
// ---------------------------------------------------------------------------

#define N_NODES 100000
#define N_EDGES 1600000
#define D_IN    128
#define D_HID   128
#define D_OUT   64

#define SCAN_NB ((N_NODES + 127) / 128)   // 782 blocks of 128 nodes

// -------------------- device scratch (no allocations allowed) --------------
__device__ int   g_i64;                 // 1 if edge indices are int64
__device__ int   g_deg[N_NODES];
__device__ int   g_rowptr[N_NODES + 1];
__device__ int   g_cursor[N_NODES];
__device__ int   g_bsum[SCAN_NB];
__device__ int   g_boff[SCAN_NB];
__device__ int   g_csrsrc[N_EDGES];
__device__ float g_agg[(size_t)N_NODES * D_IN];
__device__ float g_h[(size_t)N_NODES * D_HID];
__device__ float g_t[(size_t)N_NODES * D_OUT];

// -------------------- dtype detection --------------------------------------
// int64 values in [0, 2^31) have zero odd 32-bit words (little-endian).
__global__ void k_detect(const void* srcbuf) {
    const int* w = (const int*)srcbuf;
    __shared__ int odd_nz;
    if (threadIdx.x == 0) odd_nz = 0;
    __syncthreads();
    int bad = 0;
    for (int i = threadIdx.x; i < 1024; i += blockDim.x)
        if (w[2 * i + 1] != 0) bad = 1;           // stays within 8KB of buffer
    if (bad) atomicOr(&odd_nz, 1);
    __syncthreads();
    if (threadIdx.x == 0) g_i64 = (odd_nz == 0) ? 1 : 0;
}

__device__ __forceinline__ int idx_at(const void* p, int e, int i64) {
    return i64 ? (int)((const long long*)p)[e] : ((const int*)p)[e];
}

// -------------------- CSR build ---------------------------------------------
__global__ void k_zero_deg() {
    int i = blockIdx.x * blockDim.x + threadIdx.x;
    if (i < N_NODES) g_deg[i] = 0;
}

__global__ void k_hist(const void* dst) {
    int e = blockIdx.x * blockDim.x + threadIdx.x;
    int i64 = g_i64;
    if (e < N_EDGES) {
        int d = idx_at(dst, e, i64);
        if (d >= 0 && d < N_NODES) atomicAdd(&g_deg[d], 1);
    }
}

// phase 1: per-block (128 nodes) degree sums
__global__ __launch_bounds__(128) void k_scan_partial() {
    __shared__ int s[128];
    int t = threadIdx.x;
    int i = blockIdx.x * 128 + t;
    int d = (i < N_NODES) ? g_deg[i] : 0;
    s[t] = d;
    __syncthreads();
#pragma unroll
    for (int off = 1; off < 128; off <<= 1) {
        int v = (t >= off) ? s[t - off] : 0;
        __syncthreads();
        s[t] += v;
        __syncthreads();
    }
    if (t == 127) g_bsum[blockIdx.x] = s[127];
}

// phase 2: single-block scan over SCAN_NB block totals (<=1024)
__global__ __launch_bounds__(1024) void k_scan_tops() {
    __shared__ int s[1024];
    int t = threadIdx.x;
    int v0 = (t < SCAN_NB) ? g_bsum[t] : 0;
    s[t] = v0;
    __syncthreads();
#pragma unroll
    for (int off = 1; off < 1024; off <<= 1) {
        int v = (t >= off) ? s[t - off] : 0;
        __syncthreads();
        s[t] += v;
        __syncthreads();
    }
    if (t < SCAN_NB) g_boff[t] = s[t] - v0;        // exclusive
    if (t == 1023) g_rowptr[N_NODES] = s[1023];    // grand total
}

// phase 3: rowptr/cursor fill
__global__ __launch_bounds__(128) void k_scan_fill() {
    __shared__ int s[128];
    int t = threadIdx.x;
    int i = blockIdx.x * 128 + t;
    int d = (i < N_NODES) ? g_deg[i] : 0;
    s[t] = d;
    __syncthreads();
#pragma unroll
    for (int off = 1; off < 128; off <<= 1) {
        int v = (t >= off) ? s[t - off] : 0;
        __syncthreads();
        s[t] += v;
        __syncthreads();
    }
    if (i < N_NODES) {
        int p = g_boff[blockIdx.x] + s[t] - d;     // exclusive prefix
        g_rowptr[i] = p;
        g_cursor[i] = p;
    }
}

__global__ void k_scatter(const void* src, const void* dst) {
    int e = blockIdx.x * blockDim.x + threadIdx.x;
    int i64 = g_i64;
    if (e < N_EDGES) {
        int d = idx_at(dst, e, i64);
        int s = idx_at(src, e, i64);
        if (d >= 0 && d < N_NODES && s >= 0 && s < N_NODES) {
            int pos = atomicAdd(&g_cursor[d], 1);
            g_csrsrc[pos] = s;
        }
    }
}

// -------------------- aggregation kernels ----------------------------------
// layer 1: one warp per node, 128 floats = 32 float4 lanes, 2-deep MLP
__global__ void k_agg128(const float* __restrict__ x) {
    int gtid = blockIdx.x * blockDim.x + threadIdx.x;
    int node = gtid >> 5;
    int lane = gtid & 31;
    if (node >= N_NODES) return;
    int beg = g_rowptr[node];
    int end = g_rowptr[node + 1];
    const float4* x4 = (const float4*)x;
    float ax0 = 0.f, ay0 = 0.f, az0 = 0.f, aw0 = 0.f;
    float ax1 = 0.f, ay1 = 0.f, az1 = 0.f, aw1 = 0.f;
    int j = beg;
    for (; j + 1 < end; j += 2) {
        int s0 = g_csrsrc[j];
        int s1 = g_csrsrc[j + 1];
        float4 v0 = x4[(size_t)s0 * 32 + lane];
        float4 v1 = x4[(size_t)s1 * 32 + lane];
        ax0 += v0.x; ay0 += v0.y; az0 += v0.z; aw0 += v0.w;
        ax1 += v1.x; ay1 += v1.y; az1 += v1.z; aw1 += v1.w;
    }
    if (j < end) {
        int s0 = g_csrsrc[j];
        float4 v0 = x4[(size_t)s0 * 32 + lane];
        ax0 += v0.x; ay0 += v0.y; az0 += v0.z; aw0 += v0.w;
    }
    int deg = end - beg;
    float inv = 1.0f / (float)(deg > 0 ? deg : 1);
    float4 r = make_float4((ax0 + ax1) * inv, (ay0 + ay1) * inv,
                           (az0 + az1) * inv, (aw0 + aw1) * inv);
    ((float4*)g_agg)[(size_t)node * 32 + lane] = r;
}

// layer 2: one warp per node over g_t (64 floats = 32 float2 lanes), add to out
__global__ void k_agg64(float* __restrict__ out) {
    int gtid = blockIdx.x * blockDim.x + threadIdx.x;
    int node = gtid >> 5;
    int lane = gtid & 31;
    if (node >= N_NODES) return;
    int beg = g_rowptr[node];
    int end = g_rowptr[node + 1];
    const float2* t2 = (const float2*)g_t;
    float ax0 = 0.f, ay0 = 0.f, ax1 = 0.f, ay1 = 0.f;
    int j = beg;
    for (; j + 1 < end; j += 2) {
        int s0 = g_csrsrc[j];
        int s1 = g_csrsrc[j + 1];
        float2 v0 = t2[(size_t)s0 * 32 + lane];
        float2 v1 = t2[(size_t)s1 * 32 + lane];
        ax0 += v0.x; ay0 += v0.y;
        ax1 += v1.x; ay1 += v1.y;
    }
    if (j < end) {
        int s0 = g_csrsrc[j];
        float2 v0 = t2[(size_t)s0 * 32 + lane];
        ax0 += v0.x; ay0 += v0.y;
    }
    int deg = end - beg;
    float inv = 1.0f / (float)(deg > 0 ? deg : 1);
    float2* o2 = (float2*)out;
    float2 cur = o2[(size_t)node * 32 + lane];
    cur.x += (ax0 + ax1) * inv;
    cur.y += (ay0 + ay1) * inv;
    o2[(size_t)node * 32 + lane] = cur;
}

// -------------------- GEMM kernels (register-tiled, FFMA) ------------------
#define BM 128
#define BN 128
#define BK 16
#define TM 8
#define TN 8

// g_h = relu( x @ Ws1 + g_agg @ Wn1 + b1 ) : M=100000, N=128, K=256 ([x|agg])
// NOTE: writes g_h via direct device-code reference (NOT a kernel arg).
__global__ __launch_bounds__(256) void k_gemm1(
    const float* __restrict__ x, const float* __restrict__ Ws,
    const float* __restrict__ Wn, const float* __restrict__ bias) {
    __shared__ __align__(16) float As[BK][BM + 4];
    __shared__ __align__(16) float Bs[BK][BN];
    const int tid = threadIdx.x;
    const int tx = tid & 15;          // N direction (8 cols each)
    const int ty = tid >> 4;          // M direction (8 rows each)
    const int rowBase = blockIdx.x * BM;
    const int aRow = tid >> 1;
    const int aCol = (tid & 1) * 8;
    const int bRow = tid >> 4;        // 0..15
    const int bCol = (tid & 15) * 8;  // 0..120

    float acc[TM][TN];
#pragma unroll
    for (int i = 0; i < TM; i++)
#pragma unroll
        for (int j = 0; j < TN; j++) acc[i][j] = 0.f;

    int arow_g = rowBase + aRow;
    if (arow_g >= N_NODES) arow_g = N_NODES - 1;

    for (int kk = 0; kk < 16; ++kk) {
        const float* Aptr = (kk < 8)
            ? (x     + (size_t)arow_g * D_IN + kk * 16 + aCol)
            : (g_agg + (size_t)arow_g * D_IN + (kk - 8) * 16 + aCol);
        float4 a0 = *(const float4*)(Aptr);
        float4 a1 = *(const float4*)(Aptr + 4);
        int kg = kk * 16 + bRow;  // 0..255
        const float* Bptr = (kg < 128) ? (Ws + kg * 128 + bCol)
                                       : (Wn + (kg - 128) * 128 + bCol);
        float4 b0 = *(const float4*)(Bptr);
        float4 b1v = *(const float4*)(Bptr + 4);

        __syncthreads();
        As[aCol + 0][aRow] = a0.x; As[aCol + 1][aRow] = a0.y;
        As[aCol + 2][aRow] = a0.z; As[aCol + 3][aRow] = a0.w;
        As[aCol + 4][aRow] = a1.x; As[aCol + 5][aRow] = a1.y;
        As[aCol + 6][aRow] = a1.z; As[aCol + 7][aRow] = a1.w;
        *(float4*)&Bs[bRow][bCol] = b0;
        *(float4*)&Bs[bRow][bCol + 4] = b1v;
        __syncthreads();

#pragma unroll
        for (int k = 0; k < BK; k++) {
            float a[8], b[8];
            *(float4*)&a[0] = *(const float4*)&As[k][ty * TM];
            *(float4*)&a[4] = *(const float4*)&As[k][ty * TM + 4];
            *(float4*)&b[0] = *(const float4*)&Bs[k][tx * TN];
            *(float4*)&b[4] = *(const float4*)&Bs[k][tx * TN + 4];
#pragma unroll
            for (int i = 0; i < 8; i++)
#pragma unroll
                for (int j = 0; j < 8; j++)
                    acc[i][j] = fmaf(a[i], b[j], acc[i][j]);
        }
    }

    float bloc[8];
#pragma unroll
    for (int j = 0; j < 8; j++) bloc[j] = bias[tx * TN + j];
#pragma unroll
    for (int i = 0; i < TM; i++) {
        int r = rowBase + ty * TM + i;
        if (r < N_NODES) {
            float v[8];
#pragma unroll
            for (int j = 0; j < 8; j++) {
                float z = acc[i][j] + bloc[j];
                v[j] = z > 0.f ? z : 0.f;
            }
            float4* dst4 = (float4*)(g_h + (size_t)r * D_HID + tx * TN);
            dst4[0] = make_float4(v[0], v[1], v[2], v[3]);
            dst4[1] = make_float4(v[4], v[5], v[6], v[7]);
        }
    }
}

// [self | neigh] = g_h @ [Ws2 | Wn2] : M=100000, N=128 (64+64), K=128
// self half (+b2) -> out (harness ptr, OK as arg) ; neigh half -> g_t (direct)
__global__ __launch_bounds__(256) void k_gemm2(
    const float* __restrict__ Ws2, const float* __restrict__ Wn2,
    const float* __restrict__ bias, float* __restrict__ out) {
    __shared__ __align__(16) float As[BK][BM + 4];
    __shared__ __align__(16) float Bs[BK][BN];
    const int tid = threadIdx.x;
    const int tx = tid & 15;
    const int ty = tid >> 4;
    const int rowBase = blockIdx.x * BM;
    const int aRow = tid >> 1;
    const int aCol = (tid & 1) * 8;
    const int bRow = tid >> 4;
    const int bCol = (tid & 15) * 8;

    float acc[TM][TN];
#pragma unroll
    for (int i = 0; i < TM; i++)
#pragma unroll
        for (int j = 0; j < TN; j++) acc[i][j] = 0.f;

    int arow_g = rowBase + aRow;
    if (arow_g >= N_NODES) arow_g = N_NODES - 1;

    for (int kk = 0; kk < 8; ++kk) {
        const float* Aptr = g_h + (size_t)arow_g * D_HID + kk * 16 + aCol;
        float4 a0 = *(const float4*)(Aptr);
        float4 a1 = *(const float4*)(Aptr + 4);
        int kg = kk * 16 + bRow;  // 0..127
        const float* Bptr = (bCol < 64) ? (Ws2 + kg * 64 + bCol)
                                        : (Wn2 + kg * 64 + (bCol - 64));
        float4 b0 = *(const float4*)(Bptr);
        float4 b1v = *(const float4*)(Bptr + 4);

        __syncthreads();
        As[aCol + 0][aRow] = a0.x; As[aCol + 1][aRow] = a0.y;
        As[aCol + 2][aRow] = a0.z; As[aCol + 3][aRow] = a0.w;
        As[aCol + 4][aRow] = a1.x; As[aCol + 5][aRow] = a1.y;
        As[aCol + 6][aRow] = a1.z; As[aCol + 7][aRow] = a1.w;
        *(float4*)&Bs[bRow][bCol] = b0;
        *(float4*)&Bs[bRow][bCol + 4] = b1v;
        __syncthreads();

#pragma unroll
        for (int k = 0; k < BK; k++) {
            float a[8], b[8];
            *(float4*)&a[0] = *(const float4*)&As[k][ty * TM];
            *(float4*)&a[4] = *(const float4*)&As[k][ty * TM + 4];
            *(float4*)&b[0] = *(const float4*)&Bs[k][tx * TN];
            *(float4*)&b[4] = *(const float4*)&Bs[k][tx * TN + 4];
#pragma unroll
            for (int i = 0; i < 8; i++)
#pragma unroll
                for (int j = 0; j < 8; j++)
                    acc[i][j] = fmaf(a[i], b[j], acc[i][j]);
        }
    }

    const bool selfHalf = (tx < 8);
    float bloc[8];
#pragma unroll
    for (int j = 0; j < 8; j++) bloc[j] = selfHalf ? bias[tx * TN + j] : 0.f;
#pragma unroll
    for (int i = 0; i < TM; i++) {
        int r = rowBase + ty * TM + i;
        if (r < N_NODES) {
            float v[8];
#pragma unroll
            for (int j = 0; j < 8; j++) v[j] = acc[i][j] + bloc[j];
            float4* dst4 = selfHalf
                ? (float4*)(out + (size_t)r * D_OUT + tx * TN)
                : (float4*)(g_t + (size_t)r * D_OUT + (tx - 8) * TN);
            dst4[0] = make_float4(v[0], v[1], v[2], v[3]);
            dst4[1] = make_float4(v[4], v[5], v[6], v[7]);
        }
    }
}

// ---------------------------------------------------------------------------
extern "C" void kernel_launch(void* const* d_in, const int* in_sizes, int n_in,
                              void* d_out, int out_size) {
    const float* x   = (const float*)d_in[0];
    const void*  src = d_in[1];
    const void*  dst = d_in[2];
    const float* Ws1 = (const float*)d_in[3];
    const float* Wn1 = (const float*)d_in[4];
    const float* b1  = (const float*)d_in[5];
    const float* Ws2 = (const float*)d_in[6];
    const float* Wn2 = (const float*)d_in[7];
    const float* b2  = (const float*)d_in[8];
    float* out = (float*)d_out;

    // 0) index dtype detection
    k_detect<<<1, 256>>>(src);

    // 1) CSR build with parallel 3-phase scan
    k_zero_deg<<<(N_NODES + 255) / 256, 256>>>();
    k_hist<<<(N_EDGES + 255) / 256, 256>>>(dst);
    k_scan_partial<<<SCAN_NB, 128>>>();
    k_scan_tops<<<1, 1024>>>();
    k_scan_fill<<<SCAN_NB, 128>>>();
    k_scatter<<<(N_EDGES + 255) / 256, 256>>>(src, dst);

    // 2) layer 1
    k_agg128<<<(N_NODES * 32 + 255) / 256, 256>>>(x);
    k_gemm1<<<(N_NODES + BM - 1) / BM, 256>>>(x, Ws1, Wn1, b1);

    // 3) layer 2 (transform first, aggregate 64-wide afterwards)
    k_gemm2<<<(N_NODES + BM - 1) / BM, 256>>>(Ws2, Wn2, b2, out);
    k_agg64<<<(N_NODES * 32 + 255) / 256, 256>>>(out);
}

// round 7
// speedup vs baseline: 2.6440x; 1.0410x over previous
#include <cuda_runtime.h>
#include <cuda_bf16.h>

// ---------------------------------------------------------------------------
// SAGE 2-layer GraphSAGE, mean aggregation.
//   agg1 = mean_{src->i} x[src];  h = relu(x@Ws1 + agg1@Wn1 + b1)
//   out  = h@Ws2 + mean_{src->i} (h@Wn2)[src] + b2   (aggregation is linear)
// Index dtype (int32 vs int64) detected at runtime on-device.
// RULES: never pass __device__ globals as kernel args (R5 lesson).
// ---------------------------------------------------------------------------

#define N_NODES 100000
#define N_EDGES 1600000
#define D_IN    128
#define D_HID   128
#define D_OUT   64

#define SCAN_NB ((N_NODES + 127) / 128)   // 782 blocks of 128 nodes

// -------------------- device scratch (no allocations allowed) --------------
__device__ int   g_i64;                 // 1 if edge indices are int64
__device__ int   g_deg[N_NODES];
__device__ int   g_rowptr[N_NODES + 1];
__device__ int   g_cursor[N_NODES];
__device__ int   g_bsum[SCAN_NB];
__device__ int   g_boff[SCAN_NB];
__device__ int   g_csrsrc[N_EDGES];
__device__ float g_agg[(size_t)N_NODES * D_IN];
__device__ float g_h[(size_t)N_NODES * D_HID];
__device__ float g_t[(size_t)N_NODES * D_OUT];

// -------------------- packed f32x2 helpers (Blackwell FFMA2 pipe) ----------
__device__ __forceinline__ unsigned long long pk2(float lo, float hi) {
    unsigned long long r;
    asm("mov.b64 %0, {%1, %2};" : "=l"(r) : "f"(lo), "f"(hi));
    return r;
}
__device__ __forceinline__ void fma2(unsigned long long& d,
                                     unsigned long long a,
                                     unsigned long long b) {
    asm("fma.rn.f32x2 %0, %1, %2, %0;" : "+l"(d) : "l"(a), "l"(b));
}
__device__ __forceinline__ float2 unpk2(unsigned long long v) {
    float2 r;
    asm("mov.b64 {%0, %1}, %2;" : "=f"(r.x), "=f"(r.y) : "l"(v));
    return r;
}

// -------------------- dtype detection --------------------------------------
// int64 values in [0, 2^31) have zero odd 32-bit words (little-endian).
__global__ void k_detect(const void* srcbuf) {
    const int* w = (const int*)srcbuf;
    __shared__ int odd_nz;
    if (threadIdx.x == 0) odd_nz = 0;
    __syncthreads();
    int bad = 0;
    for (int i = threadIdx.x; i < 1024; i += blockDim.x)
        if (w[2 * i + 1] != 0) bad = 1;           // stays within 8KB of buffer
    if (bad) atomicOr(&odd_nz, 1);
    __syncthreads();
    if (threadIdx.x == 0) g_i64 = (odd_nz == 0) ? 1 : 0;
}

__device__ __forceinline__ int idx_at(const void* p, int e, int i64) {
    return i64 ? (int)((const long long*)p)[e] : ((const int*)p)[e];
}

// -------------------- CSR build ---------------------------------------------
__global__ void k_zero_deg() {
    int i = blockIdx.x * blockDim.x + threadIdx.x;
    if (i < N_NODES) g_deg[i] = 0;
}

__global__ void k_hist(const void* dst) {
    int e = blockIdx.x * blockDim.x + threadIdx.x;
    int i64 = g_i64;
    if (e < N_EDGES) {
        int d = idx_at(dst, e, i64);
        if (d >= 0 && d < N_NODES) atomicAdd(&g_deg[d], 1);
    }
}

// phase 1: per-block (128 nodes) degree sums
__global__ __launch_bounds__(128) void k_scan_partial() {
    __shared__ int s[128];
    int t = threadIdx.x;
    int i = blockIdx.x * 128 + t;
    int d = (i < N_NODES) ? g_deg[i] : 0;
    s[t] = d;
    __syncthreads();
#pragma unroll
    for (int off = 1; off < 128; off <<= 1) {
        int v = (t >= off) ? s[t - off] : 0;
        __syncthreads();
        s[t] += v;
        __syncthreads();
    }
    if (t == 127) g_bsum[blockIdx.x] = s[127];
}

// phase 2: single-block scan over SCAN_NB block totals (<=1024)
__global__ __launch_bounds__(1024) void k_scan_tops() {
    __shared__ int s[1024];
    int t = threadIdx.x;
    int v0 = (t < SCAN_NB) ? g_bsum[t] : 0;
    s[t] = v0;
    __syncthreads();
#pragma unroll
    for (int off = 1; off < 1024; off <<= 1) {
        int v = (t >= off) ? s[t - off] : 0;
        __syncthreads();
        s[t] += v;
        __syncthreads();
    }
    if (t < SCAN_NB) g_boff[t] = s[t] - v0;        // exclusive
    if (t == 1023) g_rowptr[N_NODES] = s[1023];    // grand total
}

// phase 3: rowptr/cursor fill
__global__ __launch_bounds__(128) void k_scan_fill() {
    __shared__ int s[128];
    int t = threadIdx.x;
    int i = blockIdx.x * 128 + t;
    int d = (i < N_NODES) ? g_deg[i] : 0;
    s[t] = d;
    __syncthreads();
#pragma unroll
    for (int off = 1; off < 128; off <<= 1) {
        int v = (t >= off) ? s[t - off] : 0;
        __syncthreads();
        s[t] += v;
        __syncthreads();
    }
    if (i < N_NODES) {
        int p = g_boff[blockIdx.x] + s[t] - d;     // exclusive prefix
        g_rowptr[i] = p;
        g_cursor[i] = p;
    }
}

__global__ void k_scatter(const void* src, const void* dst) {
    int e = blockIdx.x * blockDim.x + threadIdx.x;
    int i64 = g_i64;
    if (e < N_EDGES) {
        int d = idx_at(dst, e, i64);
        int s = idx_at(src, e, i64);
        if (d >= 0 && d < N_NODES && s >= 0 && s < N_NODES) {
            int pos = atomicAdd(&g_cursor[d], 1);
            g_csrsrc[pos] = s;
        }
    }
}

// -------------------- aggregation kernels ----------------------------------
// layer 1: one warp per node, 128 floats = 32 float4 lanes, 2-deep MLP
__global__ void k_agg128(const float* __restrict__ x) {
    int gtid = blockIdx.x * blockDim.x + threadIdx.x;
    int node = gtid >> 5;
    int lane = gtid & 31;
    if (node >= N_NODES) return;
    int beg = g_rowptr[node];
    int end = g_rowptr[node + 1];
    const float4* x4 = (const float4*)x;
    float ax0 = 0.f, ay0 = 0.f, az0 = 0.f, aw0 = 0.f;
    float ax1 = 0.f, ay1 = 0.f, az1 = 0.f, aw1 = 0.f;
    int j = beg;
    for (; j + 1 < end; j += 2) {
        int s0 = g_csrsrc[j];
        int s1 = g_csrsrc[j + 1];
        float4 v0 = x4[(size_t)s0 * 32 + lane];
        float4 v1 = x4[(size_t)s1 * 32 + lane];
        ax0 += v0.x; ay0 += v0.y; az0 += v0.z; aw0 += v0.w;
        ax1 += v1.x; ay1 += v1.y; az1 += v1.z; aw1 += v1.w;
    }
    if (j < end) {
        int s0 = g_csrsrc[j];
        float4 v0 = x4[(size_t)s0 * 32 + lane];
        ax0 += v0.x; ay0 += v0.y; az0 += v0.z; aw0 += v0.w;
    }
    int deg = end - beg;
    float inv = 1.0f / (float)(deg > 0 ? deg : 1);
    float4 r = make_float4((ax0 + ax1) * inv, (ay0 + ay1) * inv,
                           (az0 + az1) * inv, (aw0 + aw1) * inv);
    ((float4*)g_agg)[(size_t)node * 32 + lane] = r;
}

// layer 2: one warp per node over g_t (64 floats = 32 float2 lanes), add to out
__global__ void k_agg64(float* __restrict__ out) {
    int gtid = blockIdx.x * blockDim.x + threadIdx.x;
    int node = gtid >> 5;
    int lane = gtid & 31;
    if (node >= N_NODES) return;
    int beg = g_rowptr[node];
    int end = g_rowptr[node + 1];
    const float2* t2 = (const float2*)g_t;
    float ax0 = 0.f, ay0 = 0.f, ax1 = 0.f, ay1 = 0.f;
    int j = beg;
    for (; j + 1 < end; j += 2) {
        int s0 = g_csrsrc[j];
        int s1 = g_csrsrc[j + 1];
        float2 v0 = t2[(size_t)s0 * 32 + lane];
        float2 v1 = t2[(size_t)s1 * 32 + lane];
        ax0 += v0.x; ay0 += v0.y;
        ax1 += v1.x; ay1 += v1.y;
    }
    if (j < end) {
        int s0 = g_csrsrc[j];
        float2 v0 = t2[(size_t)s0 * 32 + lane];
        ax0 += v0.x; ay0 += v0.y;
    }
    int deg = end - beg;
    float inv = 1.0f / (float)(deg > 0 ? deg : 1);
    float2* o2 = (float2*)out;
    float2 cur = o2[(size_t)node * 32 + lane];
    cur.x += (ax0 + ax1) * inv;
    cur.y += (ay0 + ay1) * inv;
    o2[(size_t)node * 32 + lane] = cur;
}

// -------------------- GEMM kernels (register-tiled, FFMA2/f32x2) -----------
#define BM 128
#define BN 128
#define BK 16
#define TM 8
#define TN 8

// g_h = relu( x @ Ws1 + g_agg @ Wn1 + b1 ) : M=100000, N=128, K=256 ([x|agg])
__global__ __launch_bounds__(256) void k_gemm1(
    const float* __restrict__ x, const float* __restrict__ Ws,
    const float* __restrict__ Wn, const float* __restrict__ bias) {
    __shared__ __align__(16) float As[BK][BM + 4];
    __shared__ __align__(16) float Bs[BK][BN];
    const int tid = threadIdx.x;
    const int tx = tid & 15;          // N direction (8 cols each)
    const int ty = tid >> 4;          // M direction (8 rows each)
    const int rowBase = blockIdx.x * BM;
    const int aRow = tid >> 1;
    const int aCol = (tid & 1) * 8;
    const int bRow = tid >> 4;        // 0..15
    const int bCol = (tid & 15) * 8;  // 0..120

    unsigned long long acc[TM][TN / 2];
#pragma unroll
    for (int i = 0; i < TM; i++)
#pragma unroll
        for (int j = 0; j < TN / 2; j++) acc[i][j] = 0ull;

    int arow_g = rowBase + aRow;
    if (arow_g >= N_NODES) arow_g = N_NODES - 1;

    for (int kk = 0; kk < 16; ++kk) {
        const float* Aptr = (kk < 8)
            ? (x     + (size_t)arow_g * D_IN + kk * 16 + aCol)
            : (g_agg + (size_t)arow_g * D_IN + (kk - 8) * 16 + aCol);
        float4 a0 = *(const float4*)(Aptr);
        float4 a1 = *(const float4*)(Aptr + 4);
        int kg = kk * 16 + bRow;  // 0..255
        const float* Bptr = (kg < 128) ? (Ws + kg * 128 + bCol)
                                       : (Wn + (kg - 128) * 128 + bCol);
        float4 b0 = *(const float4*)(Bptr);
        float4 b1v = *(const float4*)(Bptr + 4);

        __syncthreads();
        As[aCol + 0][aRow] = a0.x; As[aCol + 1][aRow] = a0.y;
        As[aCol + 2][aRow] = a0.z; As[aCol + 3][aRow] = a0.w;
        As[aCol + 4][aRow] = a1.x; As[aCol + 5][aRow] = a1.y;
        As[aCol + 6][aRow] = a1.z; As[aCol + 7][aRow] = a1.w;
        *(float4*)&Bs[bRow][bCol] = b0;
        *(float4*)&Bs[bRow][bCol + 4] = b1v;
        __syncthreads();

#pragma unroll
        for (int k = 0; k < BK; k++) {
            float a[8], b[8];
            *(float4*)&a[0] = *(const float4*)&As[k][ty * TM];
            *(float4*)&a[4] = *(const float4*)&As[k][ty * TM + 4];
            *(float4*)&b[0] = *(const float4*)&Bs[k][tx * TN];
            *(float4*)&b[4] = *(const float4*)&Bs[k][tx * TN + 4];
            unsigned long long bb[4] = {pk2(b[0], b[1]), pk2(b[2], b[3]),
                                        pk2(b[4], b[5]), pk2(b[6], b[7])};
#pragma unroll
            for (int i = 0; i < 8; i++) {
                unsigned long long a2 = pk2(a[i], a[i]);
#pragma unroll
                for (int j = 0; j < 4; j++) fma2(acc[i][j], a2, bb[j]);
            }
        }
    }

    float bloc[8];
#pragma unroll
    for (int j = 0; j < 8; j++) bloc[j] = bias[tx * TN + j];
#pragma unroll
    for (int i = 0; i < TM; i++) {
        int r = rowBase + ty * TM + i;
        if (r < N_NODES) {
            float v[8];
#pragma unroll
            for (int j = 0; j < 4; j++) {
                float2 p = unpk2(acc[i][j]);
                v[2 * j] = p.x; v[2 * j + 1] = p.y;
            }
#pragma unroll
            for (int j = 0; j < 8; j++) {
                float z = v[j] + bloc[j];
                v[j] = z > 0.f ? z : 0.f;
            }
            float4* dst4 = (float4*)(g_h + (size_t)r * D_HID + tx * TN);
            dst4[0] = make_float4(v[0], v[1], v[2], v[3]);
            dst4[1] = make_float4(v[4], v[5], v[6], v[7]);
        }
    }
}

// [self | neigh] = g_h @ [Ws2 | Wn2] : M=100000, N=128 (64+64), K=128
__global__ __launch_bounds__(256) void k_gemm2(
    const float* __restrict__ Ws2, const float* __restrict__ Wn2,
    const float* __restrict__ bias, float* __restrict__ out) {
    __shared__ __align__(16) float As[BK][BM + 4];
    __shared__ __align__(16) float Bs[BK][BN];
    const int tid = threadIdx.x;
    const int tx = tid & 15;
    const int ty = tid >> 4;
    const int rowBase = blockIdx.x * BM;
    const int aRow = tid >> 1;
    const int aCol = (tid & 1) * 8;
    const int bRow = tid >> 4;
    const int bCol = (tid & 15) * 8;

    unsigned long long acc[TM][TN / 2];
#pragma unroll
    for (int i = 0; i < TM; i++)
#pragma unroll
        for (int j = 0; j < TN / 2; j++) acc[i][j] = 0ull;

    int arow_g = rowBase + aRow;
    if (arow_g >= N_NODES) arow_g = N_NODES - 1;

    for (int kk = 0; kk < 8; ++kk) {
        const float* Aptr = g_h + (size_t)arow_g * D_HID + kk * 16 + aCol;
        float4 a0 = *(const float4*)(Aptr);
        float4 a1 = *(const float4*)(Aptr + 4);
        int kg = kk * 16 + bRow;  // 0..127
        const float* Bptr = (bCol < 64) ? (Ws2 + kg * 64 + bCol)
                                        : (Wn2 + kg * 64 + (bCol - 64));
        float4 b0 = *(const float4*)(Bptr);
        float4 b1v = *(const float4*)(Bptr + 4);

        __syncthreads();
        As[aCol + 0][aRow] = a0.x; As[aCol + 1][aRow] = a0.y;
        As[aCol + 2][aRow] = a0.z; As[aCol + 3][aRow] = a0.w;
        As[aCol + 4][aRow] = a1.x; As[aCol + 5][aRow] = a1.y;
        As[aCol + 6][aRow] = a1.z; As[aCol + 7][aRow] = a1.w;
        *(float4*)&Bs[bRow][bCol] = b0;
        *(float4*)&Bs[bRow][bCol + 4] = b1v;
        __syncthreads();

#pragma unroll
        for (int k = 0; k < BK; k++) {
            float a[8], b[8];
            *(float4*)&a[0] = *(const float4*)&As[k][ty * TM];
            *(float4*)&a[4] = *(const float4*)&As[k][ty * TM + 4];
            *(float4*)&b[0] = *(const float4*)&Bs[k][tx * TN];
            *(float4*)&b[4] = *(const float4*)&Bs[k][tx * TN + 4];
            unsigned long long bb[4] = {pk2(b[0], b[1]), pk2(b[2], b[3]),
                                        pk2(b[4], b[5]), pk2(b[6], b[7])};
#pragma unroll
            for (int i = 0; i < 8; i++) {
                unsigned long long a2 = pk2(a[i], a[i]);
#pragma unroll
                for (int j = 0; j < 4; j++) fma2(acc[i][j], a2, bb[j]);
            }
        }
    }

    const bool selfHalf = (tx < 8);
    float bloc[8];
#pragma unroll
    for (int j = 0; j < 8; j++) bloc[j] = selfHalf ? bias[tx * TN + j] : 0.f;
#pragma unroll
    for (int i = 0; i < TM; i++) {
        int r = rowBase + ty * TM + i;
        if (r < N_NODES) {
            float v[8];
#pragma unroll
            for (int j = 0; j < 4; j++) {
                float2 p = unpk2(acc[i][j]);
                v[2 * j] = p.x; v[2 * j + 1] = p.y;
            }
#pragma unroll
            for (int j = 0; j < 8; j++) v[j] += bloc[j];
            float4* dst4 = selfHalf
                ? (float4*)(out + (size_t)r * D_OUT + tx * TN)
                : (float4*)(g_t + (size_t)r * D_OUT + (tx - 8) * TN);
            dst4[0] = make_float4(v[0], v[1], v[2], v[3]);
            dst4[1] = make_float4(v[4], v[5], v[6], v[7]);
        }
    }
}

// ---------------------------------------------------------------------------
extern "C" void kernel_launch(void* const* d_in, const int* in_sizes, int n_in,
                              void* d_out, int out_size) {
    const float* x   = (const float*)d_in[0];
    const void*  src = d_in[1];
    const void*  dst = d_in[2];
    const float* Ws1 = (const float*)d_in[3];
    const float* Wn1 = (const float*)d_in[4];
    const float* b1  = (const float*)d_in[5];
    const float* Ws2 = (const float*)d_in[6];
    const float* Wn2 = (const float*)d_in[7];
    const float* b2  = (const float*)d_in[8];
    float* out = (float*)d_out;

    // 0) index dtype detection
    k_detect<<<1, 256>>>(src);

    // 1) CSR build with parallel 3-phase scan
    k_zero_deg<<<(N_NODES + 255) / 256, 256>>>();
    k_hist<<<(N_EDGES + 255) / 256, 256>>>(dst);
    k_scan_partial<<<SCAN_NB, 128>>>();
    k_scan_tops<<<1, 1024>>>();
    k_scan_fill<<<SCAN_NB, 128>>>();
    k_scatter<<<(N_EDGES + 255) / 256, 256>>>(src, dst);

    // 2) layer 1
    k_agg128<<<(N_NODES * 32 + 255) / 256, 256>>>(x);
    k_gemm1<<<(N_NODES + BM - 1) / BM, 256>>>(x, Ws1, Wn1, b1);

    // 3) layer 2 (transform first, aggregate 64-wide afterwards)
    k_gemm2<<<(N_NODES + BM - 1) / BM, 256>>>(Ws2, Wn2, b2, out);
    k_agg64<<<(N_NODES * 32 + 255) / 256, 256>>>(out);
}